// round 16
// baseline (speedup 1.0000x reference)
#include <cuda_runtime.h>
#include <cuda_fp16.h>
#include <float.h>
#include <math.h>
#include <stdint.h>

#define N_SIMP 400000
#define E_NNZ  2400000
#define FDIM_IN 32
#define H_DIM  64
#define G_NUM  512
#define NOUT   8
#define BN_EPS 1e-5f

// ---------------------------------------------------------------------------
// Static scratch (float-typed; carved into half/float regions by byte offset)
// ---------------------------------------------------------------------------
#define NS ((size_t)N_SIMP * (size_t)H_DIM)
__device__ __align__(256) float g_scratch[NS * 8];

__device__ __align__(256) int  g_rowptrL[N_SIMP + 1];
__device__ __align__(256) int  g_rowptrU[N_SIMP + 1];
__device__ __align__(256) int  g_offsL[N_SIMP];
__device__ __align__(256) int  g_offsU[N_SIMP];
__device__ __align__(256) int  g_cnt[N_SIMP];
__device__ __align__(256) int  g_bsums[512];
__device__ __align__(256) int2 g_edgesL[E_NNZ];
__device__ __align__(256) int2 g_edgesU[E_NNZ];

struct SmallBufs {
    float bnsum0[64], bnss0[64];
    float bnsum1[64], bnss1[64];
    float pmax[G_NUM * 64];
    float psum[G_NUM * 64];
    float pcnt[G_NUM];
};
__device__ __align__(256) SmallBufs g_small;

// ---------------------------------------------------------------------------
// init small accumulators
// ---------------------------------------------------------------------------
__global__ void init_small_kernel() {
    int i = blockIdx.x * blockDim.x + threadIdx.x;
    if (i < 64) {
        g_small.bnsum0[i] = 0.f; g_small.bnss0[i] = 0.f;
        g_small.bnsum1[i] = 0.f; g_small.bnss1[i] = 0.f;
    }
    if (i < G_NUM) g_small.pcnt[i] = 0.f;
    if (i < G_NUM * 64) { g_small.pmax[i] = -FLT_MAX; g_small.psum[i] = 0.f; }
}

// ---------------------------------------------------------------------------
// CSR build
// ---------------------------------------------------------------------------
__global__ __launch_bounds__(256) void hist_kernel(
    const int* __restrict__ dst, int* __restrict__ cnt, int nE)
{
    int e = blockIdx.x * blockDim.x + threadIdx.x;
    if (e < nE) atomicAdd(&cnt[__ldg(&dst[e])], 1);
}

__global__ __launch_bounds__(256) void scan_partial(
    const int* __restrict__ cnt, int n, int* __restrict__ bsums)
{
    int b = blockIdx.x, t = threadIdx.x;
    int base = b * 1024 + t * 4;
    int s = 0;
    #pragma unroll
    for (int i = 0; i < 4; i++) { int idx = base + i; if (idx < n) s += __ldg(&cnt[idx]); }
    #pragma unroll
    for (int o = 16; o > 0; o >>= 1) s += __shfl_down_sync(0xffffffffu, s, o);
    __shared__ int ws[8];
    int lane = t & 31, wid = t >> 5;
    if (lane == 0) ws[wid] = s;
    __syncthreads();
    if (t == 0) {
        int tot = 0;
        #pragma unroll
        for (int w = 0; w < 8; w++) tot += ws[w];
        bsums[b] = tot;
    }
}

__global__ __launch_bounds__(512) void scan_bsums(int* __restrict__ bsums, int nb) {
    int t = threadIdx.x, lane = t & 31, wid = t >> 5;
    int v = (t < nb) ? bsums[t] : 0;
    int x = v;
    #pragma unroll
    for (int o = 1; o < 32; o <<= 1) {
        int y = __shfl_up_sync(0xffffffffu, x, o);
        if (lane >= o) x += y;
    }
    __shared__ int ws[16];
    if (lane == 31) ws[wid] = x;
    __syncthreads();
    if (t < 16) {
        int y = ws[t];
        #pragma unroll
        for (int o = 1; o < 16; o <<= 1) {
            int z = __shfl_up_sync(0xffffu, y, o);
            if (t >= o) y += z;
        }
        ws[t] = y;
    }
    __syncthreads();
    int incl = x + (wid > 0 ? ws[wid - 1] : 0);
    if (t < nb) bsums[t] = incl - v;
}

__global__ __launch_bounds__(256) void scan_final(
    const int* __restrict__ cnt, int n, const int* __restrict__ bsums,
    int* __restrict__ rowptr, int* __restrict__ offs, int total)
{
    int b = blockIdx.x, t = threadIdx.x;
    int base = b * 1024 + t * 4;
    int v[4]; int tsum = 0;
    #pragma unroll
    for (int i = 0; i < 4; i++) {
        v[i] = (base + i < n) ? __ldg(&cnt[base + i]) : 0;
        tsum += v[i];
    }
    int lane = t & 31, wid = t >> 5;
    int x = tsum;
    #pragma unroll
    for (int o = 1; o < 32; o <<= 1) {
        int y = __shfl_up_sync(0xffffffffu, x, o);
        if (lane >= o) x += y;
    }
    __shared__ int ws[8];
    if (lane == 31) ws[wid] = x;
    __syncthreads();
    if (t < 8) {
        int y = ws[t];
        #pragma unroll
        for (int o = 1; o < 8; o <<= 1) {
            int z = __shfl_up_sync(0xffu, y, o);
            if (t >= o) y += z;
        }
        ws[t] = y;
    }
    __syncthreads();
    int run = x - tsum + (wid > 0 ? ws[wid - 1] : 0) + __ldg(&bsums[b]);
    #pragma unroll
    for (int i = 0; i < 4; i++) {
        if (base + i < n) { rowptr[base + i] = run; offs[base + i] = run; }
        run += v[i];
    }
    if (b == 0 && t == 0) rowptr[n] = total;
}

__global__ __launch_bounds__(256) void scatter_kernel(
    const int* __restrict__ dst, const int* __restrict__ src,
    const float* __restrict__ val, int* __restrict__ offs,
    int2* __restrict__ edges, int nE)
{
    int e = blockIdx.x * blockDim.x + threadIdx.x;
    if (e >= nE) return;
    int d = __ldg(&dst[e]);
    int pos = atomicAdd(&offs[d], 1);
    edges[pos] = make_int2(__ldg(&src[e]), __float_as_int(__ldg(&val[e])));
}

// ---------------------------------------------------------------------------
// CSR SpMM: fp32 source -> fp16 dest (layer-0 first hops)
// ---------------------------------------------------------------------------
template <int F>
__global__ __launch_bounds__(256) void spmm_csr_f32src(
    const int* __restrict__ rowptr, const int2* __restrict__ edges,
    const float* __restrict__ x, half* __restrict__ y)
{
    constexpr int TPR = F / 8;
    constexpr int RPB = 256 / TPR;
    int r = blockIdx.x * RPB + threadIdx.x / TPR;
    if (r >= N_SIMP) return;
    int sub = threadIdx.x & (TPR - 1);
    int e   = __ldg(&rowptr[r]);
    int end = __ldg(&rowptr[r + 1]);

    float acc[8];
    #pragma unroll
    for (int j = 0; j < 8; j++) acc[j] = 0.f;

    for (; e < end; e++) {
        int2 ed = __ldg(&edges[e]);
        float v = __int_as_float(ed.y);
        const float4* xr = (const float4*)(x + (size_t)ed.x * F) + sub * 2;
        float4 a = __ldg(xr);
        float4 b = __ldg(xr + 1);
        acc[0] += v * a.x; acc[1] += v * a.y; acc[2] += v * a.z; acc[3] += v * a.w;
        acc[4] += v * b.x; acc[5] += v * b.y; acc[6] += v * b.z; acc[7] += v * b.w;
    }
    half2 hs[4];
    #pragma unroll
    for (int j = 0; j < 4; j++) hs[j] = __floats2half2_rn(acc[2 * j], acc[2 * j + 1]);
    ((uint4*)(y + (size_t)r * F))[sub] = *(uint4*)hs;
}

// ---------------------------------------------------------------------------
// CSR SpMM: fp16 source -> fp16 dest; fp32 accumulate
// ---------------------------------------------------------------------------
template <int F>
__global__ __launch_bounds__(256) void spmm_csr_f16(
    const int* __restrict__ rowptr, const int2* __restrict__ edges,
    const half* __restrict__ x, half* __restrict__ y)
{
    constexpr int TPR = F / 8;
    constexpr int RPB = 256 / TPR;
    int r = blockIdx.x * RPB + threadIdx.x / TPR;
    if (r >= N_SIMP) return;
    int sub = threadIdx.x & (TPR - 1);
    int e   = __ldg(&rowptr[r]);
    int end = __ldg(&rowptr[r + 1]);

    float acc[8];
    #pragma unroll
    for (int j = 0; j < 8; j++) acc[j] = 0.f;

    for (; e + 1 < end; e += 2) {
        int2 e0 = __ldg(&edges[e]);
        int2 e1 = __ldg(&edges[e + 1]);
        uint4 g0 = __ldg((const uint4*)(x + (size_t)e0.x * F) + sub);
        uint4 g1 = __ldg((const uint4*)(x + (size_t)e1.x * F) + sub);
        float v0 = __int_as_float(e0.y), v1 = __int_as_float(e1.y);
        __half2* h0 = (__half2*)&g0;
        __half2* h1 = (__half2*)&g1;
        #pragma unroll
        for (int j = 0; j < 4; j++) {
            float2 f0 = __half22float2(h0[j]);
            float2 f1 = __half22float2(h1[j]);
            acc[2 * j]     += v0 * f0.x + v1 * f1.x;
            acc[2 * j + 1] += v0 * f0.y + v1 * f1.y;
        }
    }
    if (e < end) {
        int2 e0 = __ldg(&edges[e]);
        uint4 g0 = __ldg((const uint4*)(x + (size_t)e0.x * F) + sub);
        float v0 = __int_as_float(e0.y);
        __half2* h0 = (__half2*)&g0;
        #pragma unroll
        for (int j = 0; j < 4; j++) {
            float2 f0 = __half22float2(h0[j]);
            acc[2 * j]     += v0 * f0.x;
            acc[2 * j + 1] += v0 * f0.y;
        }
    }
    half2 hs[4];
    #pragma unroll
    for (int j = 0; j < 4; j++) hs[j] = __floats2half2_rn(acc[2 * j], acc[2 * j + 1]);
    ((uint4*)(y + (size_t)r * F))[sub] = *(uint4*)hs;
}

// ---------------------------------------------------------------------------
// fp16 MMA m16n8k16, fp32 accumulate
// ---------------------------------------------------------------------------
__device__ __forceinline__ void mma_f16(float c[4], uint32_t a0, uint32_t a1,
                                        uint32_t a2, uint32_t a3,
                                        uint32_t b0, uint32_t b1) {
    asm volatile(
        "mma.sync.aligned.m16n8k16.row.col.f32.f16.f16.f32 "
        "{%0,%1,%2,%3}, {%4,%5,%6,%7}, {%8,%9}, {%0,%1,%2,%3};"
        : "+f"(c[0]), "+f"(c[1]), "+f"(c[2]), "+f"(c[3])
        : "r"(a0), "r"(a1), "r"(a2), "r"(a3), "r"(b0), "r"(b1));
}

// ---------------------------------------------------------------------------
// 7-segment concat GEMM, fp16 tensor cores (m16n8k16), BM=128.
// A tiles: half [128][40] (stride 20 words, conflict-free).
// B tiles: half [64][40], stored N-MAJOR (Bs[n][k]) so B fragments load as
// half2 of consecutive k. Seg 0 is fp32 (layer0 x) or half (layer1 Hb).
// ---------------------------------------------------------------------------
#define ASTRIDE 40
#define BSTRIDE 40

template <int FIN, bool A0F32>
__global__ __launch_bounds__(256) void gemm7_tc_kernel(
    const void* __restrict__ A0v,
    const half* __restrict__ A1, const half* __restrict__ A2,
    const half* __restrict__ A3, const half* __restrict__ A4,
    const half* __restrict__ A5, const half* __restrict__ A6,
    const float* __restrict__ Wh, const float* __restrict__ Wl,
    const float* __restrict__ Wu,
    const float* __restrict__ bh, const float* __restrict__ bl,
    const float* __restrict__ bu,
    float* __restrict__ Z)
{
    __shared__ half Ash[128][ASTRIDE];
    __shared__ half Bs[64][BSTRIDE];
    __shared__ float biasSm[64];

    const int warp = threadIdx.x >> 5;
    const int lane = threadIdx.x & 31;
    const int row0 = blockIdx.x * 128;
    const int gr = lane >> 2;
    const int gc = lane & 3;

    if (threadIdx.x < 64) {
        float s = __ldg(&bh[threadIdx.x]);
        #pragma unroll
        for (int k = 0; k < 3; k++)
            s += __ldg(&bl[k * 64 + threadIdx.x]) + __ldg(&bu[k * 64 + threadIdx.x]);
        biasSm[threadIdx.x] = s;
    }

    const half* Aseg[7] = { (const half*)A0v, A1, A2, A3, A4, A5, A6 };
    const float* Wseg[7] = { Wh,
                             Wl, Wl + FIN * 64, Wl + 2 * FIN * 64,
                             Wu, Wu + FIN * 64, Wu + 2 * FIN * 64 };

    float acc[8][4];
    #pragma unroll
    for (int t = 0; t < 8; t++)
        #pragma unroll
        for (int c = 0; c < 4; c++) acc[t][c] = 0.f;

    #pragma unroll
    for (int seg = 0; seg < 7; seg++) {
        const float* W = Wseg[seg];
        #pragma unroll
        for (int kt = 0; kt < FIN / 32; kt++) {
            const int k0 = kt * 32;
            // stage A tile 128x32 halves
            if (A0F32 && seg == 0) {
                const float* A = (const float*)A0v;
                #pragma unroll
                for (int i = 0; i < 2; i++) {
                    int idx = threadIdx.x + 256 * i;   // 0..511
                    int r  = idx >> 2;
                    int kc = (idx & 3) * 8;
                    const float4* src = (const float4*)(A + (size_t)(row0 + r) * FIN + k0 + kc);
                    float4 v0 = __ldg(src);
                    float4 v1 = __ldg(src + 1);
                    half2 hs[4];
                    hs[0] = __floats2half2_rn(v0.x, v0.y);
                    hs[1] = __floats2half2_rn(v0.z, v0.w);
                    hs[2] = __floats2half2_rn(v1.x, v1.y);
                    hs[3] = __floats2half2_rn(v1.z, v1.w);
                    *(uint4*)&Ash[r][kc] = *(uint4*)hs;
                }
            } else {
                const half* A = Aseg[seg];
                #pragma unroll
                for (int i = 0; i < 2; i++) {
                    int idx = threadIdx.x + 256 * i;
                    int r  = idx >> 2;
                    int kc = (idx & 3) * 8;
                    uint4 g = __ldg((const uint4*)(A + (size_t)(row0 + r) * FIN + k0 + kc));
                    *(uint4*)&Ash[r][kc] = g;
                }
            }
            // stage B tile: W fp32 [32 k][64 n] -> Bs[n][k] half (transposed)
            #pragma unroll
            for (int i = 0; i < 2; i++) {
                int f4 = threadIdx.x + 256 * i;    // 0..511
                int kr = f4 >> 4;                  // 0..31
                int c  = (f4 & 15) * 4;            // 0..60
                float4 v = __ldg((const float4*)(W + (size_t)(k0 + kr) * 64 + c));
                Bs[c + 0][kr] = __float2half_rn(v.x);
                Bs[c + 1][kr] = __float2half_rn(v.y);
                Bs[c + 2][kr] = __float2half_rn(v.z);
                Bs[c + 3][kr] = __float2half_rn(v.w);
            }
            __syncthreads();
            #pragma unroll
            for (int kk = 0; kk < 32; kk += 16) {
                int ar = 16 * warp + gr;
                uint32_t a0 = *(uint32_t*)&Ash[ar][kk + 2 * gc];
                uint32_t a1 = *(uint32_t*)&Ash[ar + 8][kk + 2 * gc];
                uint32_t a2 = *(uint32_t*)&Ash[ar][kk + 2 * gc + 8];
                uint32_t a3 = *(uint32_t*)&Ash[ar + 8][kk + 2 * gc + 8];
                #pragma unroll
                for (int t = 0; t < 8; t++) {
                    uint32_t b0 = *(uint32_t*)&Bs[8 * t + gr][kk + 2 * gc];
                    uint32_t b1 = *(uint32_t*)&Bs[8 * t + gr][kk + 2 * gc + 8];
                    mma_f16(acc[t], a0, a1, a2, a3, b0, b1);
                }
            }
            __syncthreads();
        }
    }

    const int cc = gc * 2;
    size_t base0 = (size_t)(row0 + 16 * warp + gr) * 64;
    size_t base1 = base0 + (size_t)8 * 64;
    #pragma unroll
    for (int t = 0; t < 8; t++) {
        int col = 8 * t + cc;
        float b0 = biasSm[col], b1 = biasSm[col + 1];
        float2 v0 = make_float2(acc[t][0] + b0, acc[t][1] + b1);
        float2 v1 = make_float2(acc[t][2] + b0, acc[t][3] + b1);
        *(float2*)(Z + base0 + col) = v0;
        *(float2*)(Z + base1 + col) = v1;
    }
}

// ---------------------------------------------------------------------------
// BN stats (reads fp32 Z)
// ---------------------------------------------------------------------------
__global__ __launch_bounds__(256) void bnstats_kernel(
    const float* __restrict__ Z, float* __restrict__ outSum,
    float* __restrict__ outSS)
{
    __shared__ float shS[4][64];
    __shared__ float shQ[4][64];
    int f  = threadIdx.x & 63;
    int rg = threadIdx.x >> 6;
    float s = 0.f, q = 0.f;
    for (int r = blockIdx.x * 4 + rg; r < N_SIMP; r += gridDim.x * 4) {
        float v = __ldg(&Z[(size_t)r * 64 + f]);
        s += v; q += v * v;
    }
    shS[rg][f] = s; shQ[rg][f] = q;
    __syncthreads();
    if (rg == 0) {
        s = shS[0][f] + shS[1][f] + shS[2][f] + shS[3][f];
        q = shQ[0][f] + shQ[1][f] + shQ[2][f] + shQ[3][f];
        atomicAdd(&outSum[f], s);
        atomicAdd(&outSS[f], q);
    }
}

// ---------------------------------------------------------------------------
// BN apply + ELU, fp32 in -> fp16 out
// ---------------------------------------------------------------------------
__device__ __forceinline__ float elu1(float v) {
    return v > 0.f ? v : expm1f(v);
}

__global__ __launch_bounds__(256) void bnapply_f16_kernel(
    const float* __restrict__ Z, const float* __restrict__ gsum,
    const float* __restrict__ gss, const float* __restrict__ gamma,
    const float* __restrict__ beta, half* __restrict__ Hout)
{
    size_t i4 = (size_t)blockIdx.x * blockDim.x + threadIdx.x;
    if (i4 >= NS / 4) return;
    int fb = ((int)(i4 & 15)) * 4;
    float4 z = __ldg((const float4*)Z + i4);
    float o[4];
    float invN = 1.f / (float)N_SIMP;
    #pragma unroll
    for (int c = 0; c < 4; c++) {
        int f = fb + c;
        float mean = __ldg(&gsum[f]) * invN;
        float var  = __ldg(&gss[f]) * invN - mean * mean;
        float sc   = rsqrtf(var + BN_EPS) * __ldg(&gamma[f]);
        float sh   = __ldg(&beta[f]);
        float v    = ((&z.x)[c] - mean) * sc + sh;
        o[c]       = elu1(v);
    }
    half2 hs[2];
    hs[0] = __floats2half2_rn(o[0], o[1]);
    hs[1] = __floats2half2_rn(o[2], o[3]);
    ((uint2*)Hout)[i4] = *(uint2*)hs;
}

// ---------------------------------------------------------------------------
// Segment pooling (reads fp16 H)
// ---------------------------------------------------------------------------
__device__ __forceinline__ void atomicMaxF(float* addr, float v) {
    int* ia = (int*)addr;
    int old = *ia;
    while (v > __int_as_float(old)) {
        int assumed = old;
        old = atomicCAS(ia, assumed, __float_as_int(v));
        if (old == assumed) break;
    }
}

#define POOL_ROWS 1000
__global__ __launch_bounds__(256) void pool_kernel(
    const half* __restrict__ Hin, const int* __restrict__ bi)
{
    int f  = threadIdx.x & 63;
    int rl = threadIdx.x >> 6;
    int r0 = blockIdx.x * POOL_ROWS;
    int r1 = r0 + POOL_ROWS; if (r1 > N_SIMP) r1 = N_SIMP;

    int cg = -1;
    float cmax = -FLT_MAX, csum = 0.f, ccnt = 0.f;
    for (int r = r0 + rl; r < r1; r += 4) {
        int g = __ldg(&bi[r]);
        if (g != cg) {
            if (cg >= 0) {
                atomicMaxF(&g_small.pmax[cg * 64 + f], cmax);
                atomicAdd(&g_small.psum[cg * 64 + f], csum);
                if (f == 0) atomicAdd(&g_small.pcnt[cg], ccnt);
            }
            cg = g; cmax = -FLT_MAX; csum = 0.f; ccnt = 0.f;
        }
        float v = __half2float(__ldg(&Hin[(size_t)r * 64 + f]));
        cmax = fmaxf(cmax, v);
        csum += v;
        ccnt += 1.f;
    }
    if (cg >= 0) {
        atomicMaxF(&g_small.pmax[cg * 64 + f], cmax);
        atomicAdd(&g_small.psum[cg * 64 + f], csum);
        if (f == 0) atomicAdd(&g_small.pcnt[cg], ccnt);
    }
}

// ---------------------------------------------------------------------------
// Final MLP
// ---------------------------------------------------------------------------
__global__ __launch_bounds__(128) void mlp_kernel(
    const float* __restrict__ W1, const float* __restrict__ b1,
    const float* __restrict__ W2, const float* __restrict__ b2,
    float* __restrict__ out)
{
    __shared__ float p[128];
    __shared__ float hid[64];
    int g = blockIdx.x;
    int t = threadIdx.x;

    if (t < 64) {
        p[t] = elu1(g_small.pmax[g * 64 + t]);
    } else {
        int f = t - 64;
        float c = g_small.pcnt[g];
        c = fmaxf(c, 1.f);
        p[t] = elu1(g_small.psum[g * 64 + f] / c);
    }
    __syncthreads();

    if (t < 64) {
        float a = __ldg(&b1[t]);
        #pragma unroll 8
        for (int i = 0; i < 128; i++) a += p[i] * __ldg(&W1[i * 64 + t]);
        hid[t] = fmaxf(a, 0.f);
    }
    __syncthreads();

    if (t < NOUT) {
        float a = __ldg(&b2[t]);
        #pragma unroll 8
        for (int j = 0; j < 64; j++) a += hid[j] * __ldg(&W2[j * NOUT + t]);
        out[g * NOUT + t] = a;
    }
}

// ---------------------------------------------------------------------------
// launch — inputs bound by (element-count, occurrence)
// ---------------------------------------------------------------------------
extern "C" void kernel_launch(void* const* d_in, const int* in_sizes, int n_in,
                              void* d_out, int out_size)
{
    const void* p4800000[2] = {0, 0};
    const void* p2400000[2] = {0, 0};
    const void* p6144[2]    = {0, 0};
    const void* p12288[2]   = {0, 0};
    const void* p192[4]     = {0, 0, 0, 0};
    const void* p64[7]      = {0, 0, 0, 0, 0, 0, 0};
    const void* p_x = 0, *p_batch = 0, *p_l0Wh = 0, *p_l1Wh = 0;
    const void* p_mlpW1 = 0, *p_mlpW2 = 0, *p_mlpb2 = 0;
    int c48 = 0, c24 = 0, c6144 = 0, c12288 = 0, c192 = 0, c64 = 0;

    for (int i = 0; i < n_in; i++) {
        int s = in_sizes[i];
        const void* p = d_in[i];
        switch (s) {
            case 12800000: p_x = p; break;
            case 4800000:  if (c48 < 2) p4800000[c48++] = p; break;
            case 2400000:  if (c24 < 2) p2400000[c24++] = p; break;
            case 400000:   p_batch = p; break;
            case 6144:     if (c6144 < 2) p6144[c6144++] = p; break;
            case 2048:     p_l0Wh = p; break;
            case 12288:    if (c12288 < 2) p12288[c12288++] = p; break;
            case 4096:     p_l1Wh = p; break;
            case 8192:     p_mlpW1 = p; break;
            case 512:      p_mlpW2 = p; break;
            case 192:      if (c192 < 4) p192[c192++] = p; break;
            case 64:       if (c64 < 7) p64[c64++] = p; break;
            case 8:        p_mlpb2 = p; break;
            default: break;
        }
    }

    const float* x      = (const float*)p_x;
    const int*   li     = (const int*)p4800000[0];
    const int*   ui     = (const int*)p4800000[1];
    const float* lv     = (const float*)p2400000[0];
    const float* uv     = (const float*)p2400000[1];
    const int*   bi     = (const int*)p_batch;
    const float* l0_Wl  = (const float*)p6144[0];
    const float* l0_Wu  = (const float*)p6144[1];
    const float* l0_Wh  = (const float*)p_l0Wh;
    const float* l1_Wl  = (const float*)p12288[0];
    const float* l1_Wu  = (const float*)p12288[1];
    const float* l1_Wh  = (const float*)p_l1Wh;
    const float* l0_bl  = (const float*)p192[0];
    const float* l0_bu  = (const float*)p192[1];
    const float* l1_bl  = (const float*)p192[2];
    const float* l1_bu  = (const float*)p192[3];
    const float* l0_bh  = (const float*)p64[0];
    const float* l1_bh  = (const float*)p64[1];
    const float* bn0_g  = (const float*)p64[2];
    const float* bn0_b  = (const float*)p64[3];
    const float* bn1_g  = (const float*)p64[4];
    const float* bn1_b  = (const float*)p64[5];
    const float* mlp_b1 = (const float*)p64[6];
    const float* mlp_W1 = (const float*)p_mlpW1;
    const float* mlp_W2 = (const float*)p_mlpW2;
    const float* mlp_b2 = (const float*)p_mlpb2;

    float* scratch = nullptr;
    cudaGetSymbolAddress((void**)&scratch, g_scratch);
    SmallBufs* sb = nullptr;
    cudaGetSymbolAddress((void**)&sb, g_small);
    int *rowptrL, *rowptrU, *offsL, *offsU, *cnt, *bsums;
    int2 *edgesL, *edgesU;
    cudaGetSymbolAddress((void**)&rowptrL, g_rowptrL);
    cudaGetSymbolAddress((void**)&rowptrU, g_rowptrU);
    cudaGetSymbolAddress((void**)&offsL, g_offsL);
    cudaGetSymbolAddress((void**)&offsU, g_offsU);
    cudaGetSymbolAddress((void**)&cnt, g_cnt);
    cudaGetSymbolAddress((void**)&bsums, g_bsums);
    cudaGetSymbolAddress((void**)&edgesL, g_edgesL);
    cudaGetSymbolAddress((void**)&edgesU, g_edgesU);

    // carve: 6 half chains, fp32 Z, half H
    char* base = (char*)scratch;
    half*  C1 = (half*)(base + 0 * NS * 2);
    half*  C2 = (half*)(base + 1 * NS * 2);
    half*  C3 = (half*)(base + 2 * NS * 2);
    half*  C4 = (half*)(base + 3 * NS * 2);
    half*  C5 = (half*)(base + 4 * NS * 2);
    half*  C6 = (half*)(base + 5 * NS * 2);
    float* Zb = (float*)(base + 6 * NS * 2);
    half*  Hb = (half*)(base + 6 * NS * 2 + NS * 4);

    const int* l_dst = li;
    const int* l_src = li + E_NNZ;
    const int* u_dst = ui;
    const int* u_src = ui + E_NNZ;

    const int SCAN_BLOCKS = (N_SIMP + 1023) / 1024;   // 391
    const int EG = (E_NNZ + 255) / 256;               // 9375

    init_small_kernel<<<128, 256>>>();

    // ---- Build CSR for lower Laplacian ----
    cudaMemsetAsync(cnt, 0, N_SIMP * sizeof(int));
    hist_kernel<<<EG, 256>>>(l_dst, cnt, E_NNZ);
    scan_partial<<<SCAN_BLOCKS, 256>>>(cnt, N_SIMP, bsums);
    scan_bsums<<<1, 512>>>(bsums, SCAN_BLOCKS);
    scan_final<<<SCAN_BLOCKS, 256>>>(cnt, N_SIMP, bsums, rowptrL, offsL, E_NNZ);
    scatter_kernel<<<EG, 256>>>(l_dst, l_src, lv, offsL, edgesL, E_NNZ);

    // ---- Build CSR for upper Laplacian ----
    cudaMemsetAsync(cnt, 0, N_SIMP * sizeof(int));
    hist_kernel<<<EG, 256>>>(u_dst, cnt, E_NNZ);
    scan_partial<<<SCAN_BLOCKS, 256>>>(cnt, N_SIMP, bsums);
    scan_bsums<<<1, 512>>>(bsums, SCAN_BLOCKS);
    scan_final<<<SCAN_BLOCKS, 256>>>(cnt, N_SIMP, bsums, rowptrU, offsU, E_NNZ);
    scatter_kernel<<<EG, 256>>>(u_dst, u_src, uv, offsU, edgesU, E_NNZ);

    // -------- Layer 0 (F = 32, chains fp16) --------
    const int G32 = (N_SIMP + 63) / 64;    // TPR=4 -> 64 rows/block
    spmm_csr_f32src<32><<<G32, 256>>>(rowptrL, edgesL, x,  C1);
    spmm_csr_f16<32><<<G32, 256>>>(rowptrL, edgesL, C1, C2);
    spmm_csr_f16<32><<<G32, 256>>>(rowptrL, edgesL, C2, C3);
    spmm_csr_f32src<32><<<G32, 256>>>(rowptrU, edgesU, x,  C4);
    spmm_csr_f16<32><<<G32, 256>>>(rowptrU, edgesU, C4, C5);
    spmm_csr_f16<32><<<G32, 256>>>(rowptrU, edgesU, C5, C6);

    gemm7_tc_kernel<32, true><<<N_SIMP / 128, 256>>>(x, C1, C2, C3, C4, C5, C6,
                                                     l0_Wh, l0_Wl, l0_Wu,
                                                     l0_bh, l0_bl, l0_bu, Zb);

    bnstats_kernel<<<512, 256>>>(Zb, sb->bnsum0, sb->bnss0);
    bnapply_f16_kernel<<<(int)((NS / 4 + 255) / 256), 256>>>(Zb, sb->bnsum0, sb->bnss0,
                                                             bn0_g, bn0_b, Hb);

    // -------- Layer 1 (F = 64, chains fp16) --------
    const int G64 = (N_SIMP + 31) / 32;    // TPR=8 -> 32 rows/block
    spmm_csr_f16<64><<<G64, 256>>>(rowptrL, edgesL, Hb, C1);
    spmm_csr_f16<64><<<G64, 256>>>(rowptrL, edgesL, C1, C2);
    spmm_csr_f16<64><<<G64, 256>>>(rowptrL, edgesL, C2, C3);
    spmm_csr_f16<64><<<G64, 256>>>(rowptrU, edgesU, Hb, C4);
    spmm_csr_f16<64><<<G64, 256>>>(rowptrU, edgesU, C4, C5);
    spmm_csr_f16<64><<<G64, 256>>>(rowptrU, edgesU, C5, C6);

    gemm7_tc_kernel<64, false><<<N_SIMP / 128, 256>>>(Hb, C1, C2, C3, C4, C5, C6,
                                                      l1_Wh, l1_Wl, l1_Wu,
                                                      l1_bh, l1_bl, l1_bu, Zb);

    bnstats_kernel<<<512, 256>>>(Zb, sb->bnsum1, sb->bnss1);
    bnapply_f16_kernel<<<(int)((NS / 4 + 255) / 256), 256>>>(Zb, sb->bnsum1, sb->bnss1,
                                                             bn1_g, bn1_b, Hb);

    // -------- Pool + MLP --------
    pool_kernel<<<(N_SIMP + POOL_ROWS - 1) / POOL_ROWS, 256>>>(Hb, bi);
    mlp_kernel<<<G_NUM, 128>>>(mlp_W1, mlp_b1, mlp_W2, mlp_b2, (float*)d_out);
}

// round 17
// speedup vs baseline: 1.1029x; 1.1029x over previous
#include <cuda_runtime.h>
#include <cuda_fp16.h>
#include <float.h>
#include <math.h>
#include <stdint.h>

#define N_SIMP 400000
#define E_NNZ  2400000
#define G_NUM  512
#define NOUT   8
#define BN_EPS 1e-5f

// ---------------------------------------------------------------------------
// Static scratch
// ---------------------------------------------------------------------------
#define NS ((size_t)N_SIMP * (size_t)H_DIMX)
#define H_DIMX 64
__device__ __align__(256) float g_scratch[(size_t)N_SIMP * 64 * 8];

__device__ __align__(256) int  g_rowptrL[N_SIMP + 1];
__device__ __align__(256) int  g_rowptrU[N_SIMP + 1];
__device__ __align__(256) int  g_offsL[N_SIMP];
__device__ __align__(256) int  g_offsU[N_SIMP];
__device__ __align__(256) int  g_cnt[2 * N_SIMP];          // L then U
__device__ __align__(256) int  g_bsums[2][512];
__device__ __align__(256) int2 g_edgesL[E_NNZ];
__device__ __align__(256) int2 g_edgesU[E_NNZ];

struct SmallBufs {
    float bnsum0[64], bnss0[64];
    float bnsum1[64], bnss1[64];
    float pmax[G_NUM * 64];
    float psum[G_NUM * 64];
    float pcnt[G_NUM];
};
__device__ __align__(256) SmallBufs g_small;

// ---------------------------------------------------------------------------
// init: small accumulators + zero both cnt arrays (replaces memsets)
// ---------------------------------------------------------------------------
__global__ __launch_bounds__(256) void init_kernel() {
    int i = blockIdx.x * blockDim.x + threadIdx.x;
    if (i < 2 * N_SIMP) g_cnt[i] = 0;
    if (i < 64) {
        g_small.bnsum0[i] = 0.f; g_small.bnss0[i] = 0.f;
        g_small.bnsum1[i] = 0.f; g_small.bnss1[i] = 0.f;
    }
    if (i < G_NUM) g_small.pcnt[i] = 0.f;
    if (i < G_NUM * 64) { g_small.pmax[i] = -FLT_MAX; g_small.psum[i] = 0.f; }
}

// ---------------------------------------------------------------------------
// Dual CSR build: one pass over edges for BOTH Laplacians
// ---------------------------------------------------------------------------
__global__ __launch_bounds__(256) void hist_dual_kernel(
    const int* __restrict__ ldst, const int* __restrict__ udst, int nE)
{
    int e = blockIdx.x * blockDim.x + threadIdx.x;
    if (e < nE) {
        atomicAdd(&g_cnt[__ldg(&ldst[e])], 1);
        atomicAdd(&g_cnt[N_SIMP + __ldg(&udst[e])], 1);
    }
}

// scan phase 1: per-block sums; grid (391, 2) — blockIdx.y = chain
__global__ __launch_bounds__(256) void scan_partial(int n)
{
    const int* cnt = g_cnt + blockIdx.y * N_SIMP;
    int b = blockIdx.x, t = threadIdx.x;
    int base = b * 1024 + t * 4;
    int s = 0;
    #pragma unroll
    for (int i = 0; i < 4; i++) { int idx = base + i; if (idx < n) s += __ldg(&cnt[idx]); }
    #pragma unroll
    for (int o = 16; o > 0; o >>= 1) s += __shfl_down_sync(0xffffffffu, s, o);
    __shared__ int ws[8];
    int lane = t & 31, wid = t >> 5;
    if (lane == 0) ws[wid] = s;
    __syncthreads();
    if (t == 0) {
        int tot = 0;
        #pragma unroll
        for (int w = 0; w < 8; w++) tot += ws[w];
        g_bsums[blockIdx.y][b] = tot;
    }
}

// scan phase 2: exclusive scan of block sums; grid (1, 2)
__global__ __launch_bounds__(512) void scan_bsums(int nb) {
    int* bsums = g_bsums[blockIdx.y];
    int t = threadIdx.x, lane = t & 31, wid = t >> 5;
    int v = (t < nb) ? bsums[t] : 0;
    int x = v;
    #pragma unroll
    for (int o = 1; o < 32; o <<= 1) {
        int y = __shfl_up_sync(0xffffffffu, x, o);
        if (lane >= o) x += y;
    }
    __shared__ int ws[16];
    if (lane == 31) ws[wid] = x;
    __syncthreads();
    if (t < 16) {
        int y = ws[t];
        #pragma unroll
        for (int o = 1; o < 16; o <<= 1) {
            int z = __shfl_up_sync(0xffffu, y, o);
            if (t >= o) y += z;
        }
        ws[t] = y;
    }
    __syncthreads();
    int incl = x + (wid > 0 ? ws[wid - 1] : 0);
    if (t < nb) bsums[t] = incl - v;
}

// scan phase 3: grid (391, 2); writes rowptr + offs per chain
__global__ __launch_bounds__(256) void scan_final(
    int n, int* __restrict__ rowptrL, int* __restrict__ offsL,
    int* __restrict__ rowptrU, int* __restrict__ offsU, int total)
{
    const int chain = blockIdx.y;
    const int* cnt = g_cnt + chain * N_SIMP;
    int* rowptr = chain ? rowptrU : rowptrL;
    int* offs   = chain ? offsU   : offsL;
    int b = blockIdx.x, t = threadIdx.x;
    int base = b * 1024 + t * 4;
    int v[4]; int tsum = 0;
    #pragma unroll
    for (int i = 0; i < 4; i++) {
        v[i] = (base + i < n) ? __ldg(&cnt[base + i]) : 0;
        tsum += v[i];
    }
    int lane = t & 31, wid = t >> 5;
    int x = tsum;
    #pragma unroll
    for (int o = 1; o < 32; o <<= 1) {
        int y = __shfl_up_sync(0xffffffffu, x, o);
        if (lane >= o) x += y;
    }
    __shared__ int ws[8];
    if (lane == 31) ws[wid] = x;
    __syncthreads();
    if (t < 8) {
        int y = ws[t];
        #pragma unroll
        for (int o = 1; o < 8; o <<= 1) {
            int z = __shfl_up_sync(0xffu, y, o);
            if (t >= o) y += z;
        }
        ws[t] = y;
    }
    __syncthreads();
    int run = x - tsum + (wid > 0 ? ws[wid - 1] : 0) + g_bsums[chain][b];
    #pragma unroll
    for (int i = 0; i < 4; i++) {
        if (base + i < n) { rowptr[base + i] = run; offs[base + i] = run; }
        run += v[i];
    }
    if (b == 0 && t == 0) rowptr[n] = total;
}

// dual scatter: one pass over edges, scatter into both CSRs
__global__ __launch_bounds__(256) void scatter_dual_kernel(
    const int* __restrict__ ldst, const int* __restrict__ lsrc,
    const float* __restrict__ lval,
    const int* __restrict__ udst, const int* __restrict__ usrc,
    const float* __restrict__ uval,
    int* __restrict__ offsL, int* __restrict__ offsU, int nE)
{
    int e = blockIdx.x * blockDim.x + threadIdx.x;
    if (e >= nE) return;
    int dl = __ldg(&ldst[e]);
    int pl = atomicAdd(&offsL[dl], 1);
    g_edgesL[pl] = make_int2(__ldg(&lsrc[e]), __float_as_int(__ldg(&lval[e])));
    int du = __ldg(&udst[e]);
    int pu = atomicAdd(&offsU[du], 1);
    g_edgesU[pu] = make_int2(__ldg(&usrc[e]), __float_as_int(__ldg(&uval[e])));
}

// ---------------------------------------------------------------------------
// Dual-chain CSR SpMM, fp32 source -> fp16 dest, 4-edge unroll
// ---------------------------------------------------------------------------
template <int F>
__global__ __launch_bounds__(256) void spmm_dual_f32src(
    const int* __restrict__ rpL, const int2* __restrict__ eL,
    const float* __restrict__ xL, half* __restrict__ yL,
    const int* __restrict__ rpU, const int2* __restrict__ eU,
    const float* __restrict__ xU, half* __restrict__ yU, int halfGrid)
{
    constexpr int TPR = F / 8;
    constexpr int RPB = 256 / TPR;
    const bool isU = blockIdx.x >= halfGrid;
    const int b = isU ? blockIdx.x - halfGrid : blockIdx.x;
    const int* rowptr = isU ? rpU : rpL;
    const int2* edges = isU ? eU : eL;
    const float* x = isU ? xU : xL;
    half* y = isU ? yU : yL;

    int r = b * RPB + threadIdx.x / TPR;
    if (r >= N_SIMP) return;
    int sub = threadIdx.x & (TPR - 1);
    int e   = __ldg(&rowptr[r]);
    int end = __ldg(&rowptr[r + 1]);

    float acc[8];
    #pragma unroll
    for (int j = 0; j < 8; j++) acc[j] = 0.f;

    for (; e + 3 < end; e += 4) {
        int2 ed[4];
        #pragma unroll
        for (int q = 0; q < 4; q++) ed[q] = __ldg(&edges[e + q]);
        #pragma unroll
        for (int q = 0; q < 4; q++) {
            float v = __int_as_float(ed[q].y);
            const float4* xr = (const float4*)(x + (size_t)ed[q].x * F) + sub * 2;
            float4 a = __ldg(xr);
            float4 bb = __ldg(xr + 1);
            acc[0] += v * a.x;  acc[1] += v * a.y;  acc[2] += v * a.z;  acc[3] += v * a.w;
            acc[4] += v * bb.x; acc[5] += v * bb.y; acc[6] += v * bb.z; acc[7] += v * bb.w;
        }
    }
    for (; e < end; e++) {
        int2 ed = __ldg(&edges[e]);
        float v = __int_as_float(ed.y);
        const float4* xr = (const float4*)(x + (size_t)ed.x * F) + sub * 2;
        float4 a = __ldg(xr);
        float4 bb = __ldg(xr + 1);
        acc[0] += v * a.x;  acc[1] += v * a.y;  acc[2] += v * a.z;  acc[3] += v * a.w;
        acc[4] += v * bb.x; acc[5] += v * bb.y; acc[6] += v * bb.z; acc[7] += v * bb.w;
    }
    half2 hs[4];
    #pragma unroll
    for (int j = 0; j < 4; j++) hs[j] = __floats2half2_rn(acc[2 * j], acc[2 * j + 1]);
    ((uint4*)(y + (size_t)r * F))[sub] = *(uint4*)hs;
}

// ---------------------------------------------------------------------------
// Dual-chain CSR SpMM, fp16 -> fp16, fp32 accumulate, 4-edge unroll
// ---------------------------------------------------------------------------
template <int F>
__global__ __launch_bounds__(256) void spmm_dual_f16(
    const int* __restrict__ rpL, const int2* __restrict__ eL,
    const half* __restrict__ xL, half* __restrict__ yL,
    const int* __restrict__ rpU, const int2* __restrict__ eU,
    const half* __restrict__ xU, half* __restrict__ yU, int halfGrid)
{
    constexpr int TPR = F / 8;
    constexpr int RPB = 256 / TPR;
    const bool isU = blockIdx.x >= halfGrid;
    const int b = isU ? blockIdx.x - halfGrid : blockIdx.x;
    const int* rowptr = isU ? rpU : rpL;
    const int2* edges = isU ? eU : eL;
    const half* x = isU ? xU : xL;
    half* y = isU ? yU : yL;

    int r = b * RPB + threadIdx.x / TPR;
    if (r >= N_SIMP) return;
    int sub = threadIdx.x & (TPR - 1);
    int e   = __ldg(&rowptr[r]);
    int end = __ldg(&rowptr[r + 1]);

    float acc[8];
    #pragma unroll
    for (int j = 0; j < 8; j++) acc[j] = 0.f;

    for (; e + 3 < end; e += 4) {
        int2 ed[4];
        uint4 g[4];
        #pragma unroll
        for (int q = 0; q < 4; q++) ed[q] = __ldg(&edges[e + q]);
        #pragma unroll
        for (int q = 0; q < 4; q++)
            g[q] = __ldg((const uint4*)(x + (size_t)ed[q].x * F) + sub);
        #pragma unroll
        for (int q = 0; q < 4; q++) {
            float v = __int_as_float(ed[q].y);
            __half2* h = (__half2*)&g[q];
            #pragma unroll
            for (int j = 0; j < 4; j++) {
                float2 f = __half22float2(h[j]);
                acc[2 * j]     += v * f.x;
                acc[2 * j + 1] += v * f.y;
            }
        }
    }
    for (; e < end; e++) {
        int2 ed = __ldg(&edges[e]);
        uint4 g = __ldg((const uint4*)(x + (size_t)ed.x * F) + sub);
        float v = __int_as_float(ed.y);
        __half2* h = (__half2*)&g;
        #pragma unroll
        for (int j = 0; j < 4; j++) {
            float2 f = __half22float2(h[j]);
            acc[2 * j]     += v * f.x;
            acc[2 * j + 1] += v * f.y;
        }
    }
    half2 hs[4];
    #pragma unroll
    for (int j = 0; j < 4; j++) hs[j] = __floats2half2_rn(acc[2 * j], acc[2 * j + 1]);
    ((uint4*)(y + (size_t)r * F))[sub] = *(uint4*)hs;
}

// ---------------------------------------------------------------------------
// fp16 MMA m16n8k16, fp32 accumulate
// ---------------------------------------------------------------------------
__device__ __forceinline__ void mma_f16(float c[4], uint32_t a0, uint32_t a1,
                                        uint32_t a2, uint32_t a3,
                                        uint32_t b0, uint32_t b1) {
    asm volatile(
        "mma.sync.aligned.m16n8k16.row.col.f32.f16.f16.f32 "
        "{%0,%1,%2,%3}, {%4,%5,%6,%7}, {%8,%9}, {%0,%1,%2,%3};"
        : "+f"(c[0]), "+f"(c[1]), "+f"(c[2]), "+f"(c[3])
        : "r"(a0), "r"(a1), "r"(a2), "r"(a3), "r"(b0), "r"(b1));
}

// ---------------------------------------------------------------------------
// 7-segment concat GEMM, fp16 tensor cores (m16n8k16), BM=128
// ---------------------------------------------------------------------------
#define ASTRIDE 40
#define BSTRIDE 40

template <int FIN, bool A0F32>
__global__ __launch_bounds__(256) void gemm7_tc_kernel(
    const void* __restrict__ A0v,
    const half* __restrict__ A1, const half* __restrict__ A2,
    const half* __restrict__ A3, const half* __restrict__ A4,
    const half* __restrict__ A5, const half* __restrict__ A6,
    const float* __restrict__ Wh, const float* __restrict__ Wl,
    const float* __restrict__ Wu,
    const float* __restrict__ bh, const float* __restrict__ bl,
    const float* __restrict__ bu,
    float* __restrict__ Z)
{
    __shared__ half Ash[128][ASTRIDE];
    __shared__ half Bs[64][BSTRIDE];
    __shared__ float biasSm[64];

    const int warp = threadIdx.x >> 5;
    const int lane = threadIdx.x & 31;
    const int row0 = blockIdx.x * 128;
    const int gr = lane >> 2;
    const int gc = lane & 3;

    if (threadIdx.x < 64) {
        float s = __ldg(&bh[threadIdx.x]);
        #pragma unroll
        for (int k = 0; k < 3; k++)
            s += __ldg(&bl[k * 64 + threadIdx.x]) + __ldg(&bu[k * 64 + threadIdx.x]);
        biasSm[threadIdx.x] = s;
    }

    const half* Aseg[7] = { (const half*)A0v, A1, A2, A3, A4, A5, A6 };
    const float* Wseg[7] = { Wh,
                             Wl, Wl + FIN * 64, Wl + 2 * FIN * 64,
                             Wu, Wu + FIN * 64, Wu + 2 * FIN * 64 };

    float acc[8][4];
    #pragma unroll
    for (int t = 0; t < 8; t++)
        #pragma unroll
        for (int c = 0; c < 4; c++) acc[t][c] = 0.f;

    #pragma unroll
    for (int seg = 0; seg < 7; seg++) {
        const float* W = Wseg[seg];
        #pragma unroll
        for (int kt = 0; kt < FIN / 32; kt++) {
            const int k0 = kt * 32;
            if (A0F32 && seg == 0) {
                const float* A = (const float*)A0v;
                #pragma unroll
                for (int i = 0; i < 2; i++) {
                    int idx = threadIdx.x + 256 * i;
                    int r  = idx >> 2;
                    int kc = (idx & 3) * 8;
                    const float4* src = (const float4*)(A + (size_t)(row0 + r) * FIN + k0 + kc);
                    float4 v0 = __ldg(src);
                    float4 v1 = __ldg(src + 1);
                    half2 hs[4];
                    hs[0] = __floats2half2_rn(v0.x, v0.y);
                    hs[1] = __floats2half2_rn(v0.z, v0.w);
                    hs[2] = __floats2half2_rn(v1.x, v1.y);
                    hs[3] = __floats2half2_rn(v1.z, v1.w);
                    *(uint4*)&Ash[r][kc] = *(uint4*)hs;
                }
            } else {
                const half* A = Aseg[seg];
                #pragma unroll
                for (int i = 0; i < 2; i++) {
                    int idx = threadIdx.x + 256 * i;
                    int r  = idx >> 2;
                    int kc = (idx & 3) * 8;
                    uint4 g = __ldg((const uint4*)(A + (size_t)(row0 + r) * FIN + k0 + kc));
                    *(uint4*)&Ash[r][kc] = g;
                }
            }
            #pragma unroll
            for (int i = 0; i < 2; i++) {
                int f4 = threadIdx.x + 256 * i;
                int kr = f4 >> 4;
                int c  = (f4 & 15) * 4;
                float4 v = __ldg((const float4*)(W + (size_t)(k0 + kr) * 64 + c));
                Bs[c + 0][kr] = __float2half_rn(v.x);
                Bs[c + 1][kr] = __float2half_rn(v.y);
                Bs[c + 2][kr] = __float2half_rn(v.z);
                Bs[c + 3][kr] = __float2half_rn(v.w);
            }
            __syncthreads();
            #pragma unroll
            for (int kk = 0; kk < 32; kk += 16) {
                int ar = 16 * warp + gr;
                uint32_t a0 = *(uint32_t*)&Ash[ar][kk + 2 * gc];
                uint32_t a1 = *(uint32_t*)&Ash[ar + 8][kk + 2 * gc];
                uint32_t a2 = *(uint32_t*)&Ash[ar][kk + 2 * gc + 8];
                uint32_t a3 = *(uint32_t*)&Ash[ar + 8][kk + 2 * gc + 8];
                #pragma unroll
                for (int t = 0; t < 8; t++) {
                    uint32_t b0 = *(uint32_t*)&Bs[8 * t + gr][kk + 2 * gc];
                    uint32_t b1 = *(uint32_t*)&Bs[8 * t + gr][kk + 2 * gc + 8];
                    mma_f16(acc[t], a0, a1, a2, a3, b0, b1);
                }
            }
            __syncthreads();
        }
    }

    const int cc = gc * 2;
    size_t base0 = (size_t)(row0 + 16 * warp + gr) * 64;
    size_t base1 = base0 + (size_t)8 * 64;
    #pragma unroll
    for (int t = 0; t < 8; t++) {
        int col = 8 * t + cc;
        float b0 = biasSm[col], b1 = biasSm[col + 1];
        float2 v0 = make_float2(acc[t][0] + b0, acc[t][1] + b1);
        float2 v1 = make_float2(acc[t][2] + b0, acc[t][3] + b1);
        *(float2*)(Z + base0 + col) = v0;
        *(float2*)(Z + base1 + col) = v1;
    }
}

// ---------------------------------------------------------------------------
// BN stats
// ---------------------------------------------------------------------------
__global__ __launch_bounds__(256) void bnstats_kernel(
    const float* __restrict__ Z, float* __restrict__ outSum,
    float* __restrict__ outSS)
{
    __shared__ float shS[4][64];
    __shared__ float shQ[4][64];
    int f  = threadIdx.x & 63;
    int rg = threadIdx.x >> 6;
    float s = 0.f, q = 0.f;
    for (int r = blockIdx.x * 4 + rg; r < N_SIMP; r += gridDim.x * 4) {
        float v = __ldg(&Z[(size_t)r * 64 + f]);
        s += v; q += v * v;
    }
    shS[rg][f] = s; shQ[rg][f] = q;
    __syncthreads();
    if (rg == 0) {
        s = shS[0][f] + shS[1][f] + shS[2][f] + shS[3][f];
        q = shQ[0][f] + shQ[1][f] + shQ[2][f] + shQ[3][f];
        atomicAdd(&outSum[f], s);
        atomicAdd(&outSS[f], q);
    }
}

// ---------------------------------------------------------------------------
// BN apply + ELU, fp32 in -> fp16 out (layer 0 only)
// ---------------------------------------------------------------------------
__device__ __forceinline__ float elu1(float v) {
    return v > 0.f ? v : expm1f(v);
}

__global__ __launch_bounds__(256) void bnapply_f16_kernel(
    const float* __restrict__ Z, const float* __restrict__ gsum,
    const float* __restrict__ gss, const float* __restrict__ gamma,
    const float* __restrict__ beta, half* __restrict__ Hout)
{
    size_t i4 = (size_t)blockIdx.x * blockDim.x + threadIdx.x;
    if (i4 >= (size_t)N_SIMP * 16) return;
    int fb = ((int)(i4 & 15)) * 4;
    float4 z = __ldg((const float4*)Z + i4);
    float o[4];
    float invN = 1.f / (float)N_SIMP;
    #pragma unroll
    for (int c = 0; c < 4; c++) {
        int f = fb + c;
        float mean = __ldg(&gsum[f]) * invN;
        float var  = __ldg(&gss[f]) * invN - mean * mean;
        float sc   = rsqrtf(var + BN_EPS) * __ldg(&gamma[f]);
        float sh   = __ldg(&beta[f]);
        float v    = ((&z.x)[c] - mean) * sc + sh;
        o[c]       = elu1(v);
    }
    half2 hs[2];
    hs[0] = __floats2half2_rn(o[0], o[1]);
    hs[1] = __floats2half2_rn(o[2], o[3]);
    ((uint2*)Hout)[i4] = *(uint2*)hs;
}

// ---------------------------------------------------------------------------
// Fused BN+ELU+pool (layer 1): reads fp32 Z, applies BN inline, pools
// ---------------------------------------------------------------------------
__device__ __forceinline__ void atomicMaxF(float* addr, float v) {
    int* ia = (int*)addr;
    int old = *ia;
    while (v > __int_as_float(old)) {
        int assumed = old;
        old = atomicCAS(ia, assumed, __float_as_int(v));
        if (old == assumed) break;
    }
}

#define POOL_ROWS 1000
__global__ __launch_bounds__(256) void pool_bn_kernel(
    const float* __restrict__ Z, const int* __restrict__ bi,
    const float* __restrict__ gsum, const float* __restrict__ gss,
    const float* __restrict__ gamma, const float* __restrict__ beta)
{
    int f  = threadIdx.x & 63;
    int rl = threadIdx.x >> 6;
    int r0 = blockIdx.x * POOL_ROWS;
    int r1 = r0 + POOL_ROWS; if (r1 > N_SIMP) r1 = N_SIMP;

    float invN = 1.f / (float)N_SIMP;
    float mean = __ldg(&gsum[f]) * invN;
    float var  = __ldg(&gss[f]) * invN - mean * mean;
    float sc   = rsqrtf(var + BN_EPS) * __ldg(&gamma[f]);
    float sh   = __ldg(&beta[f]);

    int cg = -1;
    float cmax = -FLT_MAX, csum = 0.f, ccnt = 0.f;
    for (int r = r0 + rl; r < r1; r += 4) {
        int g = __ldg(&bi[r]);
        if (g != cg) {
            if (cg >= 0) {
                atomicMaxF(&g_small.pmax[cg * 64 + f], cmax);
                atomicAdd(&g_small.psum[cg * 64 + f], csum);
                if (f == 0) atomicAdd(&g_small.pcnt[cg], ccnt);
            }
            cg = g; cmax = -FLT_MAX; csum = 0.f; ccnt = 0.f;
        }
        float z = __ldg(&Z[(size_t)r * 64 + f]);
        float v = elu1((z - mean) * sc + sh);
        cmax = fmaxf(cmax, v);
        csum += v;
        ccnt += 1.f;
    }
    if (cg >= 0) {
        atomicMaxF(&g_small.pmax[cg * 64 + f], cmax);
        atomicAdd(&g_small.psum[cg * 64 + f], csum);
        if (f == 0) atomicAdd(&g_small.pcnt[cg], ccnt);
    }
}

// ---------------------------------------------------------------------------
// Final MLP
// ---------------------------------------------------------------------------
__global__ __launch_bounds__(128) void mlp_kernel(
    const float* __restrict__ W1, const float* __restrict__ b1,
    const float* __restrict__ W2, const float* __restrict__ b2,
    float* __restrict__ out)
{
    __shared__ float p[128];
    __shared__ float hid[64];
    int g = blockIdx.x;
    int t = threadIdx.x;

    if (t < 64) {
        p[t] = elu1(g_small.pmax[g * 64 + t]);
    } else {
        int f = t - 64;
        float c = g_small.pcnt[g];
        c = fmaxf(c, 1.f);
        p[t] = elu1(g_small.psum[g * 64 + f] / c);
    }
    __syncthreads();

    if (t < 64) {
        float a = __ldg(&b1[t]);
        #pragma unroll 8
        for (int i = 0; i < 128; i++) a += p[i] * __ldg(&W1[i * 64 + t]);
        hid[t] = fmaxf(a, 0.f);
    }
    __syncthreads();

    if (t < NOUT) {
        float a = __ldg(&b2[t]);
        #pragma unroll 8
        for (int j = 0; j < 64; j++) a += hid[j] * __ldg(&W2[j * NOUT + t]);
        out[g * NOUT + t] = a;
    }
}

// ---------------------------------------------------------------------------
// launch — inputs bound by (element-count, occurrence)
// ---------------------------------------------------------------------------
extern "C" void kernel_launch(void* const* d_in, const int* in_sizes, int n_in,
                              void* d_out, int out_size)
{
    const void* p4800000[2] = {0, 0};
    const void* p2400000[2] = {0, 0};
    const void* p6144[2]    = {0, 0};
    const void* p12288[2]   = {0, 0};
    const void* p192[4]     = {0, 0, 0, 0};
    const void* p64[7]      = {0, 0, 0, 0, 0, 0, 0};
    const void* p_x = 0, *p_batch = 0, *p_l0Wh = 0, *p_l1Wh = 0;
    const void* p_mlpW1 = 0, *p_mlpW2 = 0, *p_mlpb2 = 0;
    int c48 = 0, c24 = 0, c6144 = 0, c12288 = 0, c192 = 0, c64 = 0;

    for (int i = 0; i < n_in; i++) {
        int s = in_sizes[i];
        const void* p = d_in[i];
        switch (s) {
            case 12800000: p_x = p; break;
            case 4800000:  if (c48 < 2) p4800000[c48++] = p; break;
            case 2400000:  if (c24 < 2) p2400000[c24++] = p; break;
            case 400000:   p_batch = p; break;
            case 6144:     if (c6144 < 2) p6144[c6144++] = p; break;
            case 2048:     p_l0Wh = p; break;
            case 12288:    if (c12288 < 2) p12288[c12288++] = p; break;
            case 4096:     p_l1Wh = p; break;
            case 8192:     p_mlpW1 = p; break;
            case 512:      p_mlpW2 = p; break;
            case 192:      if (c192 < 4) p192[c192++] = p; break;
            case 64:       if (c64 < 7) p64[c64++] = p; break;
            case 8:        p_mlpb2 = p; break;
            default: break;
        }
    }

    const float* x      = (const float*)p_x;
    const int*   li     = (const int*)p4800000[0];
    const int*   ui     = (const int*)p4800000[1];
    const float* lv     = (const float*)p2400000[0];
    const float* uv     = (const float*)p2400000[1];
    const int*   bi     = (const int*)p_batch;
    const float* l0_Wl  = (const float*)p6144[0];
    const float* l0_Wu  = (const float*)p6144[1];
    const float* l0_Wh  = (const float*)p_l0Wh;
    const float* l1_Wl  = (const float*)p12288[0];
    const float* l1_Wu  = (const float*)p12288[1];
    const float* l1_Wh  = (const float*)p_l1Wh;
    const float* l0_bl  = (const float*)p192[0];
    const float* l0_bu  = (const float*)p192[1];
    const float* l1_bl  = (const float*)p192[2];
    const float* l1_bu  = (const float*)p192[3];
    const float* l0_bh  = (const float*)p64[0];
    const float* l1_bh  = (const float*)p64[1];
    const float* bn0_g  = (const float*)p64[2];
    const float* bn0_b  = (const float*)p64[3];
    const float* bn1_g  = (const float*)p64[4];
    const float* bn1_b  = (const float*)p64[5];
    const float* mlp_b1 = (const float*)p64[6];
    const float* mlp_W1 = (const float*)p_mlpW1;
    const float* mlp_W2 = (const float*)p_mlpW2;
    const float* mlp_b2 = (const float*)p_mlpb2;

    float* scratch = nullptr;
    cudaGetSymbolAddress((void**)&scratch, g_scratch);
    SmallBufs* sb = nullptr;
    cudaGetSymbolAddress((void**)&sb, g_small);
    int *rowptrL, *rowptrU, *offsL, *offsU;
    int2 *edgesL, *edgesU;
    cudaGetSymbolAddress((void**)&rowptrL, g_rowptrL);
    cudaGetSymbolAddress((void**)&rowptrU, g_rowptrU);
    cudaGetSymbolAddress((void**)&offsL, g_offsL);
    cudaGetSymbolAddress((void**)&offsU, g_offsU);
    cudaGetSymbolAddress((void**)&edgesL, g_edgesL);
    cudaGetSymbolAddress((void**)&edgesU, g_edgesU);

    // carve scratch: 6 half chains, fp32 Z, half H
    size_t NSz = (size_t)N_SIMP * 64;
    char* base = (char*)scratch;
    half*  C1 = (half*)(base + 0 * NSz * 2);
    half*  C2 = (half*)(base + 1 * NSz * 2);
    half*  C3 = (half*)(base + 2 * NSz * 2);
    half*  C4 = (half*)(base + 3 * NSz * 2);
    half*  C5 = (half*)(base + 4 * NSz * 2);
    half*  C6 = (half*)(base + 5 * NSz * 2);
    float* Zb = (float*)(base + 6 * NSz * 2);
    half*  Hb = (half*)(base + 6 * NSz * 2 + NSz * 4);

    const int* l_dst = li;
    const int* l_src = li + E_NNZ;
    const int* u_dst = ui;
    const int* u_src = ui + E_NNZ;

    const int SCAN_BLOCKS = (N_SIMP + 1023) / 1024;   // 391
    const int EG = (E_NNZ + 255) / 256;               // 9375

    // init (zeros both cnt arrays + small bufs)
    init_kernel<<<(2 * N_SIMP + 255) / 256, 256>>>();

    // ---- Dual CSR build ----
    hist_dual_kernel<<<EG, 256>>>(l_dst, u_dst, E_NNZ);
    scan_partial<<<dim3(SCAN_BLOCKS, 2), 256>>>(N_SIMP);
    scan_bsums<<<dim3(1, 2), 512>>>(SCAN_BLOCKS);
    scan_final<<<dim3(SCAN_BLOCKS, 2), 256>>>(N_SIMP, rowptrL, offsL, rowptrU, offsU, E_NNZ);
    scatter_dual_kernel<<<EG, 256>>>(l_dst, l_src, lv, u_dst, u_src, uv,
                                     offsL, offsU, E_NNZ);

    // -------- Layer 0 (F = 32): dual-chain SpMM hops --------
    const int G32 = (N_SIMP + 63) / 64;    // TPR=4 -> 64 rows/block
    spmm_dual_f32src<32><<<2 * G32, 256>>>(rowptrL, edgesL, x, C1,
                                           rowptrU, edgesU, x, C4, G32);
    spmm_dual_f16<32><<<2 * G32, 256>>>(rowptrL, edgesL, C1, C2,
                                        rowptrU, edgesU, C4, C5, G32);
    spmm_dual_f16<32><<<2 * G32, 256>>>(rowptrL, edgesL, C2, C3,
                                        rowptrU, edgesU, C5, C6, G32);

    gemm7_tc_kernel<32, true><<<N_SIMP / 128, 256>>>(x, C1, C2, C3, C4, C5, C6,
                                                     l0_Wh, l0_Wl, l0_Wu,
                                                     l0_bh, l0_bl, l0_bu, Zb);

    bnstats_kernel<<<512, 256>>>(Zb, sb->bnsum0, sb->bnss0);
    bnapply_f16_kernel<<<(int)((NSz / 4 + 255) / 256), 256>>>(Zb, sb->bnsum0, sb->bnss0,
                                                              bn0_g, bn0_b, Hb);

    // -------- Layer 1 (F = 64): dual-chain SpMM hops --------
    const int G64 = (N_SIMP + 31) / 32;    // TPR=8 -> 32 rows/block
    spmm_dual_f16<64><<<2 * G64, 256>>>(rowptrL, edgesL, Hb, C1,
                                        rowptrU, edgesU, Hb, C4, G64);
    spmm_dual_f16<64><<<2 * G64, 256>>>(rowptrL, edgesL, C1, C2,
                                        rowptrU, edgesU, C4, C5, G64);
    spmm_dual_f16<64><<<2 * G64, 256>>>(rowptrL, edgesL, C2, C3,
                                        rowptrU, edgesU, C5, C6, G64);

    gemm7_tc_kernel<64, false><<<N_SIMP / 128, 256>>>(Hb, C1, C2, C3, C4, C5, C6,
                                                      l1_Wh, l1_Wl, l1_Wu,
                                                      l1_bh, l1_bl, l1_bu, Zb);

    bnstats_kernel<<<512, 256>>>(Zb, sb->bnsum1, sb->bnss1);

    // -------- Fused BN+ELU+pool, then MLP --------
    pool_bn_kernel<<<(N_SIMP + POOL_ROWS - 1) / POOL_ROWS, 256>>>(
        Zb, bi, sb->bnsum1, sb->bnss1, bn1_g, bn1_b);
    mlp_kernel<<<G_NUM, 128>>>(mlp_W1, mlp_b1, mlp_W2, mlp_b2, (float*)d_out);
}